// round 4
// baseline (speedup 1.0000x reference)
#include <cuda_runtime.h>
#include <cuda_bf16.h>
#include <math.h>

#define NN   4096
#define FF   512
#define HH   60
#define CC   4
#define CAP  64      // max nnz per row of sub_adj (mean ~8.2, Binomial(4096,0.002))

// scratch (device globals: no allocation allowed)
// NOTE: these must ONLY be referenced from device code. Passing them as kernel
// arguments from host code yields the host shadow address (and GB300's ATS
// makes that silently readable as zeros) — that was the round-1/3 bug.
__device__ float g_deg[NN];
__device__ float g_dis[NN];
__device__ int   g_cnt[NN];
__device__ int   g_cols[NN * CAP];
__device__ float g_vals[NN * CAP];
__device__ float g_Ta[NN * HH];
__device__ float g_Tb[NN * HH];

// ---------------------------------------------------------------------------
// K0: init degrees with identity contribution (A_tilde has +I, column sum +1)
__global__ void k_init() {
    int i = blockIdx.x * blockDim.x + threadIdx.x;
    if (i < NN) g_deg[i] = 1.0f;
}

// ---------------------------------------------------------------------------
// K1: scan sub_adj, build per-row edge lists (deterministic warp-ballot
// compaction), gather P_vec only at nonzero positions, sigmoid, degree accum.
__global__ void k_build(const float* __restrict__ adj, const float* __restrict__ pvec) {
    int warp = (blockIdx.x * blockDim.x + threadIdx.x) >> 5;
    int lane = threadIdx.x & 31;
    if (warp >= NN) return;
    const int row = warp;
    const float4* rp = reinterpret_cast<const float4*>(adj + (size_t)row * NN);
    int cnt = 0;
    #pragma unroll 4
    for (int it = 0; it < NN / 128; ++it) {
        float4 v = rp[it * 32 + lane];
        int jb = it * 128 + lane * 4;
        float vv[4] = {v.x, v.y, v.z, v.w};
        #pragma unroll
        for (int q = 0; q < 4; ++q) {
            bool nz = (vv[q] != 0.0f);
            unsigned m = __ballot_sync(0xffffffffu, nz);
            if (nz) {
                int j = jb + q;
                int slot = cnt + __popc(m & ((1u << lane) - 1u));
                int a = row > j ? row : j;
                int b = row > j ? j : row;
                // tril_indices row-major: index of (a,b), a>=b, is a*(a+1)/2 + b
                float p = pvec[(size_t)a * (a + 1) / 2 + b];
                float s = vv[q] / (1.0f + expf(-p));   // sigmoid(p) * adj value
                if (slot < CAP) {
                    g_cols[row * CAP + slot] = j;
                    g_vals[row * CAP + slot] = s;
                }
                atomicAdd(&g_deg[j], s);               // column sum
            }
            cnt += __popc(m);
        }
    }
    if (lane == 0) g_cnt[row] = cnt < CAP ? cnt : CAP;
}

// ---------------------------------------------------------------------------
// K2: dis = d^{-1/2} (d >= 1 always, identity guarantees d > 0)
__global__ void k_dis() {
    int i = blockIdx.x * blockDim.x + threadIdx.x;
    if (i < NN) {
        float d = g_deg[i];
        g_dis[i] = (d > 0.0f) ? rsqrtf(d) : 0.0f;
    }
}

// ---------------------------------------------------------------------------
// K3: T1 = x @ W1 -> g_Ta   (4096x512 @ 512x60)
// block = 256 threads = 4 groups x 64 lanes; block covers 16 rows; k-tiled via smem.
__global__ void k_xw(const float* __restrict__ x, const float* __restrict__ W) {
    __shared__ float xs[16][64];
    int t = threadIdx.x;
    int r0 = blockIdx.x * 16;
    int c = t & 63;       // output column
    int g = t >> 6;       // row group (4 rows each)
    float acc[4] = {0.f, 0.f, 0.f, 0.f};
    for (int k0 = 0; k0 < FF; k0 += 64) {
        int idx = t * 4;
        int rr = idx >> 6, kk = idx & 63;
        *reinterpret_cast<float4*>(&xs[rr][kk]) =
            *reinterpret_cast<const float4*>(&x[(size_t)(r0 + rr) * FF + k0 + kk]);
        __syncthreads();
        if (c < HH) {
            #pragma unroll
            for (int kk4 = 0; kk4 < 16; ++kk4) {
                int k = kk4 * 4;
                float w0 = W[(size_t)(k0 + k + 0) * HH + c];
                float w1 = W[(size_t)(k0 + k + 1) * HH + c];
                float w2 = W[(size_t)(k0 + k + 2) * HH + c];
                float w3 = W[(size_t)(k0 + k + 3) * HH + c];
                #pragma unroll
                for (int r = 0; r < 4; ++r) {
                    float4 xr = *reinterpret_cast<const float4*>(&xs[g * 4 + r][k]);
                    acc[r] += xr.x * w0 + xr.y * w1 + xr.z * w2 + xr.w * w3;
                }
            }
        }
        __syncthreads();
    }
    if (c < HH) {
        #pragma unroll
        for (int r = 0; r < 4; ++r)
            g_Ta[(size_t)(r0 + g * 4 + r) * HH + c] = acc[r];
    }
}

// ---------------------------------------------------------------------------
// K4: fused  H = relu(SpMM(norm_adj, Tin) + bias);  Tout = H @ Wnext
// block = 256 = 4 groups x 64 lanes, one row per group.
// src/dst select the device-global ping-pong buffers FROM DEVICE CODE.
__global__ void k_layer(int src, const float* __restrict__ bias,
                        const float* __restrict__ Wnext) {
    const float* __restrict__ Tin = src ? g_Tb : g_Ta;
    float* __restrict__ Tout      = src ? g_Ta : g_Tb;
    __shared__ float hs[4][HH];
    int t = threadIdx.x, c = t & 63, g = t >> 6;
    int row = blockIdx.x * 4 + g;
    float dis_i = g_dis[row];
    if (c < HH) {
        float acc = dis_i * dis_i * Tin[(size_t)row * HH + c];  // +I self term
        int cnt = g_cnt[row];
        for (int e = 0; e < cnt; ++e) {
            int col = g_cols[row * CAP + e];
            float w = dis_i * g_vals[row * CAP + e] * g_dis[col];
            acc += w * Tin[(size_t)col * HH + c];
        }
        hs[g][c] = fmaxf(acc + bias[c], 0.0f);
    }
    __syncthreads();
    if (c < HH) {
        float o = 0.0f;
        #pragma unroll 4
        for (int k = 0; k < HH; ++k)
            o += hs[g][k] * Wnext[(size_t)k * HH + c];
        Tout[(size_t)row * HH + c] = o;
    }
}

// ---------------------------------------------------------------------------
// K5: final layer: H3 = SpMM(g_Ta) + b3 (no relu); logits = H3 @ lin_w + lin_b;
//     out = log_softmax(logits)
__global__ void k_final(const float* __restrict__ b3,
                        const float* __restrict__ lw, const float* __restrict__ lb,
                        float* __restrict__ out) {
    const float* __restrict__ Tin = g_Ta;
    __shared__ float hs[4][HH];
    __shared__ float lg[4][CC];
    int t = threadIdx.x, c = t & 63, g = t >> 6;
    int row = blockIdx.x * 4 + g;
    float dis_i = g_dis[row];
    if (c < HH) {
        float acc = dis_i * dis_i * Tin[(size_t)row * HH + c];
        int cnt = g_cnt[row];
        for (int e = 0; e < cnt; ++e) {
            int col = g_cols[row * CAP + e];
            float w = dis_i * g_vals[row * CAP + e] * g_dis[col];
            acc += w * Tin[(size_t)col * HH + c];
        }
        hs[g][c] = acc + b3[c];
    }
    __syncthreads();
    if (c < CC) {
        float o = lb[c];
        #pragma unroll 4
        for (int k = 0; k < HH; ++k)
            o += hs[g][k] * lw[(size_t)k * CC + c];
        lg[g][c] = o;
    }
    __syncthreads();
    if (c < CC) {
        float m = fmaxf(fmaxf(lg[g][0], lg[g][1]), fmaxf(lg[g][2], lg[g][3]));
        float s = expf(lg[g][0] - m) + expf(lg[g][1] - m) +
                  expf(lg[g][2] - m) + expf(lg[g][3] - m);
        out[(size_t)row * CC + c] = lg[g][c] - m - logf(s);
    }
}

// ---------------------------------------------------------------------------
// Inputs resolved BY ELEMENT COUNT (robust to metadata ordering); same-size
// ties (W2/W3, b1/b2/b3) resolved by relative order, preserved by any stable
// canonicalization.
extern "C" void kernel_launch(void* const* d_in, const int* in_sizes, int n_in,
                              void* d_out, int out_size) {
    const float *x = 0, *adj = 0, *pvec = 0, *W1 = 0, *b1 = 0, *W2 = 0, *b2 = 0,
                *W3 = 0, *b3 = 0, *lin_w = 0, *lin_b = 0;
    int nb = 0, nw = 0;
    for (int i = 0; i < n_in; ++i) {
        const float* p = (const float*)d_in[i];
        switch (in_sizes[i]) {
            case NN * FF:            x = p;    break;   // 2097152
            case NN * NN:            adj = p;  break;   // 16777216
            case (NN * (NN + 1)) / 2: pvec = p; break;  // 8390656
            case FF * HH:            W1 = p;   break;   // 30720
            case HH * HH:                                // 3600 (x2)
                if (nw == 0) W2 = p; else W3 = p;
                ++nw; break;
            case HH:                                     // 60 (x3)
                if (nb == 0) b1 = p; else if (nb == 1) b2 = p; else b3 = p;
                ++nb; break;
            case HH * CC:            lin_w = p; break;  // 240
            case CC:                 lin_b = p; break;  // 4
            default: break;
        }
    }
    float* out = (float*)d_out;

    k_init<<<NN / 256, 256>>>();
    k_build<<<NN / 8, 256>>>(adj, pvec);          // 8 warps/block, 1 warp/row
    k_dis<<<NN / 256, 256>>>();
    k_xw<<<NN / 16, 256>>>(x, W1);                // g_Ta = x@W1
    k_layer<<<NN / 4, 256>>>(0, b1, W2);          // reads g_Ta -> writes g_Tb (= h1@W2)
    k_layer<<<NN / 4, 256>>>(1, b2, W3);          // reads g_Tb -> writes g_Ta (= h2@W3)
    k_final<<<NN / 4, 256>>>(b3, lin_w, lin_b, out);
}

// round 5
// speedup vs baseline: 1.2742x; 1.2742x over previous
#include <cuda_runtime.h>
#include <cuda_bf16.h>
#include <math.h>

#define NN   4096
#define FF   512
#define HH   60
#define CC   4
#define CAP  64      // max nnz per row of sub_adj (mean ~8.2, Binomial(4096,0.002))

// scratch (device globals; referenced ONLY from device code — see R3 post-mortem)
__device__ float g_deg[NN];          // zero at module load; reset to 0 by k_xw each run
__device__ float g_dis[NN];
__device__ int   g_cnt[NN];
__device__ int   g_cols[NN * CAP];
__device__ float g_vals[NN * CAP];
__device__ float g_Ta[NN * HH];
__device__ float g_Tb[NN * HH];

__device__ __forceinline__ void cp16(unsigned s, const void* g) {
    asm volatile("cp.async.cg.shared.global [%0], [%1], 16;\n" :: "r"(s), "l"(g));
}

// ---------------------------------------------------------------------------
// K1: scan sub_adj, build per-row edge lists (deterministic warp-ballot
// compaction), gather P_vec only at nonzero positions, sigmoid, degree accum.
// g_deg starts at 0 (identity's +1 is applied in k_xw's rsqrt prologue).
__global__ void k_build(const float* __restrict__ adj, const float* __restrict__ pvec) {
    int warp = (blockIdx.x * blockDim.x + threadIdx.x) >> 5;
    int lane = threadIdx.x & 31;
    if (warp >= NN) return;
    const int row = warp;
    const float4* rp = reinterpret_cast<const float4*>(adj + (size_t)row * NN);
    int cnt = 0;
    #pragma unroll 4
    for (int it = 0; it < NN / 128; ++it) {
        float4 v = rp[it * 32 + lane];
        int jb = it * 128 + lane * 4;
        float vv[4] = {v.x, v.y, v.z, v.w};
        #pragma unroll
        for (int q = 0; q < 4; ++q) {
            bool nz = (vv[q] != 0.0f);
            unsigned m = __ballot_sync(0xffffffffu, nz);
            if (nz) {
                int j = jb + q;
                int slot = cnt + __popc(m & ((1u << lane) - 1u));
                int a = row > j ? row : j;
                int b = row > j ? j : row;
                // tril_indices row-major: index of (a,b), a>=b, is a*(a+1)/2 + b
                float p = pvec[(size_t)a * (a + 1) / 2 + b];
                float s = vv[q] / (1.0f + expf(-p));   // sigmoid(p) * adj value
                if (slot < CAP) {
                    g_cols[row * CAP + slot] = j;
                    g_vals[row * CAP + slot] = s;
                }
                atomicAdd(&g_deg[j], s);               // column sum
            }
            cnt += __popc(m);
        }
    }
    if (lane == 0) g_cnt[row] = cnt < CAP ? cnt : CAP;
}

// ---------------------------------------------------------------------------
// K2: g_Ta = x @ W1   (4096x512 @ 512x60), tiled, cp.async double-buffered,
// packed f32x2 accumulation. grid=128 blocks x 256 threads.
// Prologue also computes g_dis = (deg+1)^{-1/2} and resets g_deg (graph replay).
__global__ void __launch_bounds__(256) k_xw(const float* __restrict__ x,
                                            const float* __restrict__ W) {
    // --- degree finalize (runs after k_build; 32768 threads cover 4096) ---
    int gid = blockIdx.x * 256 + threadIdx.x;
    if (gid < NN) {
        g_dis[gid] = rsqrtf(g_deg[gid] + 1.0f);  // +1: identity self-loop
        g_deg[gid] = 0.0f;                       // reset for next graph replay
    }

    __shared__ float As[2][32][36];   // [buf][row][k], stride 36 (16B-aligned cp.async, conflict-free reads)
    __shared__ float Ws[2][32][64];   // [buf][k][col], cols 60..63 stay zero

    const int t  = threadIdx.x;
    const int tx = t & 15;            // col group: 4 cols each
    const int ty = t >> 4;            // row group: 2 rows each
    const int r0 = blockIdx.x * 32;

    // zero pad cols 60..63 (2 bufs x 32 rows x 4 = 256 writes, 1/thread)
    { int b = t >> 7, rr = (t >> 2) & 31, cc = 60 + (t & 3); Ws[b][rr][cc] = 0.0f; }

    // staging coords
    const int arow = t >> 3;          // 0..31
    const int akk  = (t & 7) * 4;     // 0,4,..,28
    const int wk   = t >> 3;          // 0..31
    const int wc   = (t & 7) * 8;     // 0,8,..,56

    auto issue = [&](int tile, int buf) {
        int k0 = tile * 32;
        unsigned sA = (unsigned)__cvta_generic_to_shared(&As[buf][arow][akk]);
        cp16(sA, x + (size_t)(r0 + arow) * FF + k0 + akk);
        unsigned sW = (unsigned)__cvta_generic_to_shared(&Ws[buf][wk][wc]);
        cp16(sW, W + (size_t)(k0 + wk) * HH + wc);
        if (wc + 4 < HH)
            cp16(sW + 16, W + (size_t)(k0 + wk) * HH + wc + 4);
        asm volatile("cp.async.commit_group;\n");
    };

    unsigned long long acc[2][2] = {{0ull, 0ull}, {0ull, 0ull}};  // [row i][col pair j]

    issue(0, 0);
    int buf = 0;
    for (int tile = 0; tile < FF / 32; ++tile) {
        __syncthreads();                       // prev compute on buf^1 done -> safe to overwrite
        if (tile < FF / 32 - 1) {
            issue(tile + 1, buf ^ 1);
            asm volatile("cp.async.wait_group 1;\n");
        } else {
            asm volatile("cp.async.wait_group 0;\n");
        }
        __syncthreads();                       // tile's data visible to all
        #pragma unroll
        for (int k = 0; k < 32; ++k) {
            unsigned a0 = __float_as_uint(As[buf][2 * ty + 0][k]);
            unsigned a1 = __float_as_uint(As[buf][2 * ty + 1][k]);
            unsigned long long pa0, pa1;
            asm("mov.b64 %0, {%1, %1};" : "=l"(pa0) : "r"(a0));
            asm("mov.b64 %0, {%1, %1};" : "=l"(pa1) : "r"(a1));
            ulonglong2 w = *reinterpret_cast<const ulonglong2*>(&Ws[buf][k][4 * tx]);
            asm("fma.rn.f32x2 %0, %1, %2, %0;" : "+l"(acc[0][0]) : "l"(pa0), "l"(w.x));
            asm("fma.rn.f32x2 %0, %1, %2, %0;" : "+l"(acc[0][1]) : "l"(pa0), "l"(w.y));
            asm("fma.rn.f32x2 %0, %1, %2, %0;" : "+l"(acc[1][0]) : "l"(pa1), "l"(w.x));
            asm("fma.rn.f32x2 %0, %1, %2, %0;" : "+l"(acc[1][1]) : "l"(pa1), "l"(w.y));
        }
        buf ^= 1;
    }

    if (4 * tx < HH) {
        #pragma unroll
        for (int i = 0; i < 2; ++i) {
            unsigned lo0, hi0, lo1, hi1;
            asm("mov.b64 {%0, %1}, %2;" : "=r"(lo0), "=r"(hi0) : "l"(acc[i][0]));
            asm("mov.b64 {%0, %1}, %2;" : "=r"(lo1), "=r"(hi1) : "l"(acc[i][1]));
            float4 o = make_float4(__uint_as_float(lo0), __uint_as_float(hi0),
                                   __uint_as_float(lo1), __uint_as_float(hi1));
            int r = r0 + 2 * ty + i;
            *reinterpret_cast<float4*>(&g_Ta[(size_t)r * HH + 4 * tx]) = o;
        }
    }
}

// ---------------------------------------------------------------------------
// K3: fused  H = relu(SpMM(norm_adj, Tin) + bias);  Tout = H @ Wnext
// block = 256 = 4 groups x 64 lanes, one row per group.
__global__ void k_layer(int src, const float* __restrict__ bias,
                        const float* __restrict__ Wnext) {
    const float* __restrict__ Tin = src ? g_Tb : g_Ta;
    float* __restrict__ Tout      = src ? g_Ta : g_Tb;
    __shared__ float hs[4][HH];
    int t = threadIdx.x, c = t & 63, g = t >> 6;
    int row = blockIdx.x * 4 + g;
    float dis_i = g_dis[row];
    if (c < HH) {
        float acc = dis_i * dis_i * Tin[(size_t)row * HH + c];  // +I self term
        int cnt = g_cnt[row];
        for (int e = 0; e < cnt; ++e) {
            int col = g_cols[row * CAP + e];
            float w = dis_i * g_vals[row * CAP + e] * g_dis[col];
            acc += w * Tin[(size_t)col * HH + c];
        }
        hs[g][c] = fmaxf(acc + bias[c], 0.0f);
    }
    __syncthreads();
    if (c < HH) {
        float o = 0.0f;
        #pragma unroll 4
        for (int k = 0; k < HH; ++k)
            o += hs[g][k] * Wnext[(size_t)k * HH + c];
        Tout[(size_t)row * HH + c] = o;
    }
}

// ---------------------------------------------------------------------------
// K4: final layer: H3 = SpMM(g_Ta) + b3 (no relu); logits = H3 @ lin_w + lin_b;
//     out = log_softmax(logits)
__global__ void k_final(const float* __restrict__ b3,
                        const float* __restrict__ lw, const float* __restrict__ lb,
                        float* __restrict__ out) {
    const float* __restrict__ Tin = g_Ta;
    __shared__ float hs[4][HH];
    __shared__ float lg[4][CC];
    int t = threadIdx.x, c = t & 63, g = t >> 6;
    int row = blockIdx.x * 4 + g;
    float dis_i = g_dis[row];
    if (c < HH) {
        float acc = dis_i * dis_i * Tin[(size_t)row * HH + c];
        int cnt = g_cnt[row];
        for (int e = 0; e < cnt; ++e) {
            int col = g_cols[row * CAP + e];
            float w = dis_i * g_vals[row * CAP + e] * g_dis[col];
            acc += w * Tin[(size_t)col * HH + c];
        }
        hs[g][c] = acc + b3[c];
    }
    __syncthreads();
    if (c < CC) {
        float o = lb[c];
        #pragma unroll 4
        for (int k = 0; k < HH; ++k)
            o += hs[g][k] * lw[(size_t)k * CC + c];
        lg[g][c] = o;
    }
    __syncthreads();
    if (c < CC) {
        float m = fmaxf(fmaxf(lg[g][0], lg[g][1]), fmaxf(lg[g][2], lg[g][3]));
        float s = expf(lg[g][0] - m) + expf(lg[g][1] - m) +
                  expf(lg[g][2] - m) + expf(lg[g][3] - m);
        out[(size_t)row * CC + c] = lg[g][c] - m - logf(s);
    }
}

// ---------------------------------------------------------------------------
// Inputs resolved BY ELEMENT COUNT (robust to metadata ordering); same-size
// ties (W2/W3, b1/b2/b3) resolved by relative order.
extern "C" void kernel_launch(void* const* d_in, const int* in_sizes, int n_in,
                              void* d_out, int out_size) {
    const float *x = 0, *adj = 0, *pvec = 0, *W1 = 0, *b1 = 0, *W2 = 0, *b2 = 0,
                *W3 = 0, *b3 = 0, *lin_w = 0, *lin_b = 0;
    int nb = 0, nw = 0;
    for (int i = 0; i < n_in; ++i) {
        const float* p = (const float*)d_in[i];
        switch (in_sizes[i]) {
            case NN * FF:            x = p;    break;   // 2097152
            case NN * NN:            adj = p;  break;   // 16777216
            case (NN * (NN + 1)) / 2: pvec = p; break;  // 8390656
            case FF * HH:            W1 = p;   break;   // 30720
            case HH * HH:                                // 3600 (x2)
                if (nw == 0) W2 = p; else W3 = p;
                ++nw; break;
            case HH:                                     // 60 (x3)
                if (nb == 0) b1 = p; else if (nb == 1) b2 = p; else b3 = p;
                ++nb; break;
            case HH * CC:            lin_w = p; break;  // 240
            case CC:                 lin_b = p; break;  // 4
            default: break;
        }
    }
    float* out = (float*)d_out;

    k_build<<<NN / 8, 256>>>(adj, pvec);   // 1 warp/row
    k_xw<<<NN / 32, 256>>>(x, W1);         // g_Ta = x@W1 (+ dis finalize)
    k_layer<<<NN / 4, 256>>>(0, b1, W2);   // g_Ta -> g_Tb
    k_layer<<<NN / 4, 256>>>(1, b2, W3);   // g_Tb -> g_Ta
    k_final<<<NN / 4, 256>>>(b3, lin_w, lin_b, out);
}